// round 15
// baseline (speedup 1.0000x reference)
#include <cuda_runtime.h>
#include <math.h>

#define NB 2
#define NC 14
#define NCLS 13          // classes 1..13
#define NPAIR (NB*NCLS)  // 26
#define NCTA 128
#define NTHR 512
// gT: row-major u8 distances [144 rows][132 cols]; rows 0..7, 136..143 = 255
#define GCOLS 132
#define GPAD 8

// per-(src,b,cls) seg bitmaps, 512 words each
__device__ unsigned g_seg[2 * NB * NCLS * 512];
// per-(b,cls) student logit>0.5 bitmaps
__device__ unsigned g_gt05[NB * NCLS * 512];
__device__ float g_part[NPAIR * 4];
__device__ int   g_counter = 0;   // finish counter (self-resetting)
__device__ int   g_cnt     = 0;   // barrier ticket counter (self-resetting)
__device__ int   g_release = 0;   // barrier sense flag (flips each launch)

__global__ void __launch_bounds__(NTHR, 1)
fused_kernel(const float* __restrict__ stud,
             const float* __restrict__ teach,
             float* __restrict__ out) {
    extern __shared__ unsigned char smem[];
    // [0,19008)        gT u8 distances (incl. padding rows)
    // [19008,21056)    Sm seed bitmap (512 u32)
    // [21056,53824)    list (u16 x 16384); early alias: segS/segT/g05 (6 KB)
    unsigned char*  gT   = smem;
    unsigned*       Sm   = (unsigned*)(smem + 19008);
    unsigned short* list = (unsigned short*)(smem + 21056);
    unsigned*       segS = (unsigned*)(smem + 21056);
    unsigned*       segT = segS + 512;
    unsigned*       g05  = segT + 512;
    __shared__ float s_warp[16];
    __shared__ int   s_wsum[16];

    int t   = threadIdx.x;
    int bid = blockIdx.x;

    // read barrier sense BEFORE any arrival can flip it
    int my_sense = 0;
    if (t == 0) my_sense = *(volatile int*)&g_release;

    // ---- Stage A: argmax + direct bitmap emission via ballots ----
    {
        int gid = bid * NTHR + t;            // 0..65535, exactly covers all slots
        int src = gid >> 15;
        int rem = gid & 32767;               // b*16384 + pix
        int b   = rem >> 14;
        int pix = rem & 16383;
        const float* base = (src ? teach : stud) +
                            (size_t)b * NC * 16384 + pix;
        float v[NC];
#pragma unroll
        for (int c = 0; c < NC; c++) v[c] = base[(size_t)c * 16384];
        float best = v[0];
        int bi = 0;
#pragma unroll
        for (int c = 1; c < NC; c++)
            if (v[c] > best) { best = v[c]; bi = c; }

        int word = pix >> 5;
        int lane0 = ((t & 31) == 0);
        unsigned* segbase = g_seg + (size_t)((src * NB + b) * NCLS) * 512 + word;
#pragma unroll
        for (int c = 1; c < NC; c++) {
            unsigned m = __ballot_sync(0xffffffffu, bi == c);
            if (lane0) segbase[(c - 1) * 512] = m;
        }
        if (src == 0) {                      // student: logit>0.5 bitmaps
            unsigned* gbase = g_gt05 + (size_t)(b * NCLS) * 512 + word;
#pragma unroll
            for (int c = 1; c < NC; c++) {
                unsigned m = __ballot_sync(0xffffffffu, v[c] > 0.5f);
                if (lane0) gbase[(c - 1) * 512] = m;
            }
        }
    }

    // ---- grid-wide sense-reversing barrier (128 co-resident CTAs) ----
    __threadfence();
    __syncthreads();
    if (t == 0) {
        __threadfence();
        int ticket = atomicAdd(&g_cnt, 1);
        if (ticket == NCTA - 1) {
            g_cnt = 0;
            __threadfence();
            atomicExch(&g_release, my_sense ^ 1);
        } else {
            while (*(volatile int*)&g_release == my_sense) __nanosleep(32);
        }
        __threadfence();
    }
    __syncthreads();

    if (bid >= NPAIR * 4) return;            // 24 helper CTAs done

    // ---- Stage B: one CTA per (pair, pass) ----
    int pair = bid >> 2;
    int pass = bid & 3;
    int b    = pair / NCLS;
    int cls  = 1 + (pair % NCLS);

    // load the three bitmaps (1 word per thread)
    segS[t] = g_seg[(size_t)((0 * NB + b) * NCLS + cls - 1) * 512 + t];
    segT[t] = g_seg[(size_t)((1 * NB + b) * NCLS + cls - 1) * 512 + t];
    g05[t]  = g_gt05[(size_t)(b * NCLS + cls - 1) * 512 + t];

    // fill gT padding rows with 255 (exactly 264 u32 words per region)
    {
        unsigned* p32 = (unsigned*)gT;
        if (t < 264) {
            p32[t] = 0xFFFFFFFFu;             // rows [0,8)
            p32[4488 + t] = 0xFFFFFFFFu;      // rows [136,144)
        }
    }
    __syncthreads();

    // word-parallel erosion: word t = (row t>>2, quarter t&3)
    int row = t >> 2, w = t & 3;
    unsigned ew, tw;
    {
        unsigned cs = segS[t];
        unsigned up = (row > 0)   ? segS[t - 4] : 0u;
        unsigned dn = (row < 127) ? segS[t + 4] : 0u;
        unsigned lf = (cs << 1) | (w > 0 ? (segS[t - 1] >> 31) : 0u);
        unsigned rg = (cs >> 1) | (w < 3 ? (segS[t + 1] << 31) : 0u);
        ew = cs & ~(cs & up & dn & lf & rg);

        unsigned ct = segT[t];
        unsigned u2 = (row > 0)   ? segT[t - 4] : 0u;
        unsigned d2 = (row < 127) ? segT[t + 4] : 0u;
        unsigned l2 = (ct << 1) | (w > 0 ? (segT[t - 1] >> 31) : 0u);
        unsigned r2 = (ct >> 1) | (w < 3 ? (segT[t + 1] << 31) : 0u);
        tw = ct & ~(ct & u2 & d2 & l2 & r2);
    }

    // seed bitmap for this pass (all-register)
    // pass 0: fgP = es & gt05   pass 1: ~fgP   pass 2: et   pass 3: ~et
    unsigned inv = (pass & 1) ? 0xffffffffu : 0u;
    unsigned sv  = ((pass < 2) ? (ew & g05[t]) : tw) ^ inv;
    Sm[t] = sv;
    // barrier: after this, seg/g05 region is dead -> list may overwrite
    int any = __syncthreads_or(sv != 0u);

    int jbase = w * 32;
    const float* lgb = stud + (size_t)(b * NC + cls) * 16384;

    // ---- Compaction: deterministic list of pixels where diff2 != 0 ----
    int n_tot;
    {
        unsigned m = ew | tw;
        int cnt = __popc(m);
        int lane = t & 31, wid = t >> 5;
        int pre = cnt;
#pragma unroll
        for (int o = 1; o < 32; o <<= 1) {
            int v = __shfl_up_sync(0xffffffffu, pre, o);
            if (lane >= o) pre += v;
        }
        if (lane == 31) s_wsum[wid] = pre;
        __syncthreads();
        int wbase = 0;
        for (int k = 0; k < wid; k++) wbase += s_wsum[k];
        n_tot = 0;
#pragma unroll
        for (int k = 0; k < 16; k++) n_tot += s_wsum[k];
        int ofs = wbase + pre - cnt;
        while (m) {
            int bit = __ffs(m) - 1;
            m &= m - 1;
            int j = jbase + bit;
            list[ofs++] = (unsigned short)(((unsigned)row << 9) |
                                           ((unsigned)j << 2)   |
                                           ((ew >> bit) & 1u)   |
                                           (((tw >> bit) & 1u) << 1));
        }
    }

    // ---- Phase 1: horizontal 1D nearest-seed distance, serial ±1 scans ----
    {
        int ri = t & 127;
        int qd = t >> 7;
        unsigned W[4];
#pragma unroll
        for (int k = 0; k < 4; k++) W[k] = Sm[ri * 4 + k];
        unsigned Wq = W[qd];
        int lpos = -100000;
        for (int k = qd - 1; k >= 0; k--)
            if (W[k]) { lpos = 32 * k + (31 - __clz(W[k])); break; }
        int rpos = 100000;
        for (int k = qd + 1; k < 4; k++)
            if (W[k]) { rpos = 32 * k + (__ffs(W[k]) - 1); break; }

        int jb = qd * 32;
        int dist[32];
        int d = jb - 1 - lpos;
#pragma unroll
        for (int jj = 0; jj < 32; jj++) {
            d++;
            if ((Wq >> jj) & 1u) d = 0;
            dist[jj] = d;
        }
        int e = rpos - jb - 32;
#pragma unroll
        for (int jj = 31; jj >= 0; jj--) {
            e++;
            if ((Wq >> jj) & 1u) e = 0;
            dist[jj] = min(dist[jj], e);
        }
        unsigned* dst = (unsigned*)(gT + (ri + GPAD) * GCOLS + jb);
#pragma unroll
        for (int p = 0; p < 8; p++) {
            unsigned pk = 0;
#pragma unroll
            for (int h = 0; h < 4; h++) {
                unsigned bb = (unsigned)min(dist[4 * p + h], 255); // >127 => INF
                pk |= bb << (8 * h);
            }
            dst[p] = pk;
        }
    }
    __syncthreads();   // list + gT complete

    // ---- Phase 2: branchless R=6 vertical search (seeds fall out as 0) ----
    // All probe addresses are valid (padding rows), so loads issue
    // unconditionally; unroll-2 interleaves two entries' probe batches.
    float acc = 0.f;
    if (any) {
        float fcls = (float)cls;
#pragma unroll 2
        for (int k = t; k < n_tot; k += NTHR) {
            unsigned e = list[k];
            int i = e >> 9;
            int j = (e >> 2) & 127;
            const unsigned char* g = gT + (i + GPAD) * GCOLS + j;
            int g0 = g[0];
            int m1 = min((int)g[ 1 * GCOLS], (int)g[-1 * GCOLS]);
            int m2 = min((int)g[ 2 * GCOLS], (int)g[-2 * GCOLS]);
            int m3 = min((int)g[ 3 * GCOLS], (int)g[-3 * GCOLS]);
            int m4 = min((int)g[ 4 * GCOLS], (int)g[-4 * GCOLS]);
            int m5 = min((int)g[ 5 * GCOLS], (int)g[-5 * GCOLS]);
            int m6 = min((int)g[ 6 * GCOLS], (int)g[-6 * GCOLS]);
            float pred = (e & 1u) ? lgb[i * 128 + j] : 0.f;
            float targ = (e & 2u) ? fcls : 0.f;
            int best = g0 * g0;
            best = min(best, m1 * m1 + 1);
            best = min(best, m2 * m2 + 4);
            best = min(best, m3 * m3 + 9);
            best = min(best, m4 * m4 + 16);
            best = min(best, m5 * m5 + 25);
            best = min(best, m6 * m6 + 36);
            if (best > 49 && g0 != 0) {   // rare exact fallback beyond R=6
#pragma unroll 1
                for (int r = 7; r * r < best; r++) {
                    int lo = (r <= i + GPAD)      ? (int)g[-r * GCOLS] : 255;
                    int hi = (i + r < 128 + GPAD) ? (int)g[ r * GCOLS] : 255;
                    int v = min(lo, hi);
                    best = min(best, v * v + r * r);
                }
            }
            float dt2 = (best < 40000) ? (float)best : 0.f;
            float d = pred - targ;
            acc += d * d * dt2;
        }
    }

    // warp-shuffle reduction
#pragma unroll
    for (int o = 16; o; o >>= 1) acc += __shfl_down_sync(0xffffffffu, acc, o);
    if ((t & 31) == 0) s_warp[t >> 5] = acc;
    __syncthreads();

    // ---- finish: last CTA's warp 0 does the parallel log-combine ----
    if (t < 32) {
        if (t == 0) {
            float tot = 0.f;
#pragma unroll
            for (int k = 0; k < 16; k++) tot += s_warp[k];
            g_part[bid] = tot;
            __threadfence();
        }
        int last = 0;
        if (t == 0) last = (atomicAdd(&g_counter, 1) == NPAIR * 4 - 1);
        last = __shfl_sync(0xffffffffu, last, 0);
        if (last) {
            __threadfence();
            float v = 0.f;
            if (t < NPAIR) {
                volatile float* vp = g_part;
                float hd = (vp[4 * t + 0] + vp[4 * t + 1] +
                            vp[4 * t + 2] + vp[4 * t + 3]) * (1.f / 16384.f);
                v = logf(hd + 1.f);
            }
#pragma unroll
            for (int o = 16; o; o >>= 1)
                v += __shfl_down_sync(0xffffffffu, v, o);
            if (t == 0) {
                out[0] = 0.5f * v;   // (1 - LOSS_WEIGHT) * sum
                g_counter = 0;       // self-reset -> deterministic replays
            }
        }
    }
}

extern "C" void kernel_launch(void* const* d_in, const int* in_sizes, int n_in,
                              void* d_out, int out_size) {
    const float* stud  = (const float*)d_in[0];
    const float* teach = (const float*)d_in[1];
    float* out = (float*)d_out;

    const int SMEM = 19008 + 2048 + 32768;   // 53824 B dynamic
    cudaFuncSetAttribute(fused_kernel,
                         cudaFuncAttributeMaxDynamicSharedMemorySize, SMEM);
    fused_kernel<<<NCTA, NTHR, SMEM>>>(stud, teach, out);
}

// round 16
// speedup vs baseline: 1.0173x; 1.0173x over previous
#include <cuda_runtime.h>
#include <math.h>

#define NB 2
#define NC 14
#define NCLS 13          // classes 1..13
#define NPAIR (NB*NCLS)  // 26
#define NCTA 128
#define NTHR 512
// gT: row-major u8 distances [144 rows][132 cols]; rows 0..7, 136..143 = 255
#define GCOLS 132
#define GPAD 8

// per-(src,b,cls) seg bitmaps, 512 words each
__device__ unsigned g_seg[2 * NB * NCLS * 512];
// per-(b,cls) student logit>0.5 bitmaps
__device__ unsigned g_gt05[NB * NCLS * 512];
__device__ float g_part[NPAIR * 4];
__device__ int   g_counter = 0;   // finish counter (self-resetting)
__device__ int   g_cnt     = 0;   // barrier ticket counter (self-resetting)
__device__ int   g_release = 0;   // barrier sense flag (flips each launch)

// expand 8 bits to stride-4 positions: bit k -> bit 4k
__device__ __forceinline__ unsigned mexp4(unsigned x) {
    x = (x | (x << 12)) & 0x000F000Fu;
    x = (x | (x << 6))  & 0x03030303u;
    x = (x | (x << 3))  & 0x11111111u;
    return x;
}

// word w from 4 ballots: bit (4k+p) = bit (8w+k) of ballot_p
__device__ __forceinline__ unsigned asm_word(unsigned p0, unsigned p1,
                                             unsigned p2, unsigned p3, int w) {
    int sh = 8 * w;
    return  mexp4((p0 >> sh) & 0xFFu)
         | (mexp4((p1 >> sh) & 0xFFu) << 1)
         | (mexp4((p2 >> sh) & 0xFFu) << 2)
         | (mexp4((p3 >> sh) & 0xFFu) << 3);
}

__global__ void __launch_bounds__(NTHR, 1)
fused_kernel(const float* __restrict__ stud,
             const float* __restrict__ teach,
             float* __restrict__ out) {
    extern __shared__ unsigned char smem[];
    // [0,19008)        gT u8 distances (incl. padding rows)
    // [19008,21056)    Sm seed bitmap (512 u32)
    // [21056,53824)    list (u16 x 16384); early alias: segS/segT/g05 (6 KB)
    unsigned char*  gT   = smem;
    unsigned*       Sm   = (unsigned*)(smem + 19008);
    unsigned short* list = (unsigned short*)(smem + 21056);
    unsigned*       segS = (unsigned*)(smem + 21056);
    unsigned*       segT = segS + 512;
    unsigned*       g05  = segT + 512;
    __shared__ float s_warp[16];
    __shared__ int   s_wsum[16];

    int t   = threadIdx.x;
    int bid = blockIdx.x;
    int lane = t & 31, wd = t >> 5;

    // read barrier sense BEFORE any arrival can flip it
    int my_sense = 0;
    if (t == 0) my_sense = *(volatile int*)&g_release;

    // ---- Stage A: 4 wide warps/CTA, float4 loads, ballot+interleave ----
    if (wd < 4) {
        int wg  = bid * 4 + wd;              // global warp 0..511
        int src = wg >> 8;
        int b   = (wg >> 7) & 1;
        int blk = wg & 127;                  // 128-px block within image
        const float4* base =
            (const float4*)((src ? teach : stud) + (size_t)b * NC * 16384)
            + blk * 32 + lane;               // pixel 4*(blk*32+lane)

        float4 v[NC];                        // front-batched: MLP = 14
#pragma unroll
        for (int c = 0; c < NC; c++) v[c] = base[(size_t)c * 4096];

        float c0 = v[0].x, c1 = v[0].y, c2 = v[0].z, c3 = v[0].w;
        int   n0 = 0, n1 = 0, n2 = 0, n3 = 0;
#pragma unroll
        for (int c = 1; c < NC; c++) {
            if (v[c].x > c0) { c0 = v[c].x; n0 = c; }
            if (v[c].y > c1) { c1 = v[c].y; n1 = c; }
            if (v[c].z > c2) { c2 = v[c].z; n2 = c; }
            if (v[c].w > c3) { c3 = v[c].w; n3 = c; }
        }

        unsigned* segbase =
            g_seg + (size_t)((src * NB + b) * NCLS) * 512 + blk * 4;
#pragma unroll
        for (int c = 1; c < NC; c++) {
            unsigned p0 = __ballot_sync(0xffffffffu, n0 == c);
            unsigned p1 = __ballot_sync(0xffffffffu, n1 == c);
            unsigned p2 = __ballot_sync(0xffffffffu, n2 == c);
            unsigned p3 = __ballot_sync(0xffffffffu, n3 == c);
            if (lane < 4)
                segbase[(c - 1) * 512 + lane] = asm_word(p0, p1, p2, p3, lane);
        }
        if (src == 0) {                      // student: logit>0.5 bitmaps
            unsigned* gbase =
                g_gt05 + (size_t)(b * NCLS) * 512 + blk * 4;
#pragma unroll
            for (int c = 1; c < NC; c++) {
                unsigned p0 = __ballot_sync(0xffffffffu, v[c].x > 0.5f);
                unsigned p1 = __ballot_sync(0xffffffffu, v[c].y > 0.5f);
                unsigned p2 = __ballot_sync(0xffffffffu, v[c].z > 0.5f);
                unsigned p3 = __ballot_sync(0xffffffffu, v[c].w > 0.5f);
                if (lane < 4)
                    gbase[(c - 1) * 512 + lane] = asm_word(p0, p1, p2, p3, lane);
            }
        }
    }

    // ---- grid-wide sense-reversing barrier (128 co-resident CTAs) ----
    __threadfence();
    __syncthreads();
    if (t == 0) {
        __threadfence();
        int ticket = atomicAdd(&g_cnt, 1);
        if (ticket == NCTA - 1) {
            g_cnt = 0;
            __threadfence();
            atomicExch(&g_release, my_sense ^ 1);
        } else {
            while (*(volatile int*)&g_release == my_sense) __nanosleep(32);
        }
        __threadfence();
    }
    __syncthreads();

    if (bid >= NPAIR * 4) return;            // 24 helper CTAs done

    // ---- Stage B: one CTA per (pair, pass) ----
    int pair = bid >> 2;
    int pass = bid & 3;
    int b    = pair / NCLS;
    int cls  = 1 + (pair % NCLS);

    // load the three bitmaps (1 word per thread)
    segS[t] = g_seg[(size_t)((0 * NB + b) * NCLS + cls - 1) * 512 + t];
    segT[t] = g_seg[(size_t)((1 * NB + b) * NCLS + cls - 1) * 512 + t];
    g05[t]  = g_gt05[(size_t)(b * NCLS + cls - 1) * 512 + t];

    // fill gT padding rows with 255 (exactly 264 u32 words per region)
    {
        unsigned* p32 = (unsigned*)gT;
        if (t < 264) {
            p32[t] = 0xFFFFFFFFu;             // rows [0,8)
            p32[4488 + t] = 0xFFFFFFFFu;      // rows [136,144)
        }
    }
    __syncthreads();

    // word-parallel erosion: word t = (row t>>2, quarter t&3)
    int row = t >> 2, w = t & 3;
    unsigned ew, tw;
    {
        unsigned cs = segS[t];
        unsigned up = (row > 0)   ? segS[t - 4] : 0u;
        unsigned dn = (row < 127) ? segS[t + 4] : 0u;
        unsigned lf = (cs << 1) | (w > 0 ? (segS[t - 1] >> 31) : 0u);
        unsigned rg = (cs >> 1) | (w < 3 ? (segS[t + 1] << 31) : 0u);
        ew = cs & ~(cs & up & dn & lf & rg);

        unsigned ct = segT[t];
        unsigned u2 = (row > 0)   ? segT[t - 4] : 0u;
        unsigned d2 = (row < 127) ? segT[t + 4] : 0u;
        unsigned l2 = (ct << 1) | (w > 0 ? (segT[t - 1] >> 31) : 0u);
        unsigned r2 = (ct >> 1) | (w < 3 ? (segT[t + 1] << 31) : 0u);
        tw = ct & ~(ct & u2 & d2 & l2 & r2);
    }

    // seed bitmap for this pass (all-register)
    // pass 0: fgP = es & gt05   pass 1: ~fgP   pass 2: et   pass 3: ~et
    unsigned inv = (pass & 1) ? 0xffffffffu : 0u;
    unsigned sv  = ((pass < 2) ? (ew & g05[t]) : tw) ^ inv;
    Sm[t] = sv;
    // barrier: after this, seg/g05 region is dead -> list may overwrite
    int any = __syncthreads_or(sv != 0u);

    int jbase = w * 32;
    const float* lgb = stud + (size_t)(b * NC + cls) * 16384;

    // ---- Compaction: deterministic list of pixels where diff2 != 0 ----
    int n_tot;
    {
        unsigned m = ew | tw;
        int cnt = __popc(m);
        int pre = cnt;
#pragma unroll
        for (int o = 1; o < 32; o <<= 1) {
            int v = __shfl_up_sync(0xffffffffu, pre, o);
            if (lane >= o) pre += v;
        }
        if (lane == 31) s_wsum[wd] = pre;
        __syncthreads();
        int wbase = 0;
        for (int k = 0; k < wd; k++) wbase += s_wsum[k];
        n_tot = 0;
#pragma unroll
        for (int k = 0; k < 16; k++) n_tot += s_wsum[k];
        int ofs = wbase + pre - cnt;
        while (m) {
            int bit = __ffs(m) - 1;
            m &= m - 1;
            int j = jbase + bit;
            list[ofs++] = (unsigned short)(((unsigned)row << 9) |
                                           ((unsigned)j << 2)   |
                                           ((ew >> bit) & 1u)   |
                                           (((tw >> bit) & 1u) << 1));
        }
    }

    // ---- Phase 1: horizontal 1D nearest-seed distance, serial ±1 scans ----
    {
        int ri = t & 127;
        int qd = t >> 7;
        unsigned W[4];
#pragma unroll
        for (int k = 0; k < 4; k++) W[k] = Sm[ri * 4 + k];
        unsigned Wq = W[qd];
        int lpos = -100000;
        for (int k = qd - 1; k >= 0; k--)
            if (W[k]) { lpos = 32 * k + (31 - __clz(W[k])); break; }
        int rpos = 100000;
        for (int k = qd + 1; k < 4; k++)
            if (W[k]) { rpos = 32 * k + (__ffs(W[k]) - 1); break; }

        int jb = qd * 32;
        int dist[32];
        int d = jb - 1 - lpos;
#pragma unroll
        for (int jj = 0; jj < 32; jj++) {
            d++;
            if ((Wq >> jj) & 1u) d = 0;
            dist[jj] = d;
        }
        int e = rpos - jb - 32;
#pragma unroll
        for (int jj = 31; jj >= 0; jj--) {
            e++;
            if ((Wq >> jj) & 1u) e = 0;
            dist[jj] = min(dist[jj], e);
        }
        unsigned* dst = (unsigned*)(gT + (ri + GPAD) * GCOLS + jb);
#pragma unroll
        for (int p = 0; p < 8; p++) {
            unsigned pk = 0;
#pragma unroll
            for (int h = 0; h < 4; h++) {
                unsigned bb = (unsigned)min(dist[4 * p + h], 255); // >127 => INF
                pk |= bb << (8 * h);
            }
            dst[p] = pk;
        }
    }
    __syncthreads();   // list + gT complete

    // ---- Phase 2: seed-skip + g0==1 shortcut + R=6 search + fallback ----
    float acc = 0.f;
    if (any) {
        float fcls = (float)cls;
        for (int k = t; k < n_tot; k += NTHR) {
            unsigned e = list[k];
            int i = e >> 9;
            int j = (e >> 2) & 127;
            const unsigned char* g = gT + (i + GPAD) * GCOLS + j;
            int g0 = g[0];
            if (g0 == 0) continue;           // seed pixel: dt2 = 0
            float pred = (e & 1u) ? lgb[i * 128 + j] : 0.f;
            float targ = (e & 2u) ? fcls : 0.f;
            int best;
            if (g0 == 1) {
                best = 1;                    // all r>=1 candidates are >= 1
            } else {
                int m1 = min((int)g[ 1 * GCOLS], (int)g[-1 * GCOLS]);
                int m2 = min((int)g[ 2 * GCOLS], (int)g[-2 * GCOLS]);
                int m3 = min((int)g[ 3 * GCOLS], (int)g[-3 * GCOLS]);
                int m4 = min((int)g[ 4 * GCOLS], (int)g[-4 * GCOLS]);
                int m5 = min((int)g[ 5 * GCOLS], (int)g[-5 * GCOLS]);
                int m6 = min((int)g[ 6 * GCOLS], (int)g[-6 * GCOLS]);
                best = g0 * g0;
                best = min(best, m1 * m1 + 1);
                best = min(best, m2 * m2 + 4);
                best = min(best, m3 * m3 + 9);
                best = min(best, m4 * m4 + 16);
                best = min(best, m5 * m5 + 25);
                best = min(best, m6 * m6 + 36);
                if (best > 49) {   // exact fallback beyond R=6
#pragma unroll 1
                    for (int r = 7; r * r < best; r++) {
                        int lo = (r <= i + GPAD)      ? (int)g[-r * GCOLS] : 255;
                        int hi = (i + r < 128 + GPAD) ? (int)g[ r * GCOLS] : 255;
                        int v = min(lo, hi);
                        best = min(best, v * v + r * r);
                    }
                }
            }
            float dt2 = (best < 40000) ? (float)best : 0.f;
            float d = pred - targ;
            acc += d * d * dt2;
        }
    }

    // warp-shuffle reduction
#pragma unroll
    for (int o = 16; o; o >>= 1) acc += __shfl_down_sync(0xffffffffu, acc, o);
    if (lane == 0) s_warp[wd] = acc;
    __syncthreads();

    // ---- finish: last CTA's warp 0 does the parallel log-combine ----
    if (t < 32) {
        if (t == 0) {
            float tot = 0.f;
#pragma unroll
            for (int k = 0; k < 16; k++) tot += s_warp[k];
            g_part[bid] = tot;
            __threadfence();
        }
        int last = 0;
        if (t == 0) last = (atomicAdd(&g_counter, 1) == NPAIR * 4 - 1);
        last = __shfl_sync(0xffffffffu, last, 0);
        if (last) {
            __threadfence();
            float v = 0.f;
            if (t < NPAIR) {
                volatile float* vp = g_part;
                float hd = (vp[4 * t + 0] + vp[4 * t + 1] +
                            vp[4 * t + 2] + vp[4 * t + 3]) * (1.f / 16384.f);
                v = logf(hd + 1.f);
            }
#pragma unroll
            for (int o = 16; o; o >>= 1)
                v += __shfl_down_sync(0xffffffffu, v, o);
            if (t == 0) {
                out[0] = 0.5f * v;   // (1 - LOSS_WEIGHT) * sum
                g_counter = 0;       // self-reset -> deterministic replays
            }
        }
    }
}

extern "C" void kernel_launch(void* const* d_in, const int* in_sizes, int n_in,
                              void* d_out, int out_size) {
    const float* stud  = (const float*)d_in[0];
    const float* teach = (const float*)d_in[1];
    float* out = (float*)d_out;

    const int SMEM = 19008 + 2048 + 32768;   // 53824 B dynamic
    cudaFuncSetAttribute(fused_kernel,
                         cudaFuncAttributeMaxDynamicSharedMemorySize, SMEM);
    fused_kernel<<<NCTA, NTHR, SMEM>>>(stud, teach, out);
}

// round 17
// speedup vs baseline: 1.0217x; 1.0043x over previous
#include <cuda_runtime.h>
#include <math.h>

#define NB 2
#define NC 14
#define NCLS 13          // classes 1..13
#define NPAIR (NB*NCLS)  // 26
#define NCTA 128
#define NTHR 512
// gT: row-major u8 distances [144 rows][132 cols]; rows 0..7, 136..143 = 255
#define GCOLS 132
#define GPAD 8

// per-(src,b,cls) seg bitmaps, 512 words each
__device__ unsigned g_seg[2 * NB * NCLS * 512];
// per-(b,cls) student logit>0.5 bitmaps
__device__ unsigned g_gt05[NB * NCLS * 512];
__device__ float g_part[NPAIR * 4];
__device__ int   g_counter = 0;   // finish counter (self-resetting)
__device__ int   g_cnt     = 0;   // barrier ticket counter (self-resetting)
__device__ int   g_release = 0;   // barrier sense flag (flips each launch)

__global__ void __launch_bounds__(NTHR, 1)
fused_kernel(const float* __restrict__ stud,
             const float* __restrict__ teach,
             float* __restrict__ out) {
    extern __shared__ unsigned char smem[];
    // [0,19008)        gT u8 distances (incl. padding rows)
    // [19008,21056)    Sm seed bitmap (512 u32)
    // [21056,53824)    list (u16 x 16384); early alias: segS/segT/g05 (6 KB)
    unsigned char*  gT   = smem;
    unsigned*       Sm   = (unsigned*)(smem + 19008);
    unsigned short* list = (unsigned short*)(smem + 21056);
    unsigned*       segS = (unsigned*)(smem + 21056);
    unsigned*       segT = segS + 512;
    unsigned*       g05  = segT + 512;
    __shared__ float s_warp[16];
    __shared__ int   s_wsum[16];

    int t   = threadIdx.x;
    int bid = blockIdx.x;

    // read barrier sense BEFORE any arrival can flip it
    int my_sense = 0;
    if (t == 0) my_sense = *(volatile int*)&g_release;

    // ---- Stage A: argmax + direct bitmap emission via ballots ----
    {
        int gid = bid * NTHR + t;            // 0..65535, exactly covers all slots
        int src = gid >> 15;
        int rem = gid & 32767;               // b*16384 + pix
        int b   = rem >> 14;
        int pix = rem & 16383;
        const float* base = (src ? teach : stud) +
                            (size_t)b * NC * 16384 + pix;
        float v[NC];
#pragma unroll
        for (int c = 0; c < NC; c++) v[c] = base[(size_t)c * 16384];
        float best = v[0];
        int bi = 0;
#pragma unroll
        for (int c = 1; c < NC; c++)
            if (v[c] > best) { best = v[c]; bi = c; }

        int word = pix >> 5;
        int lane0 = ((t & 31) == 0);
        unsigned* segbase = g_seg + (size_t)((src * NB + b) * NCLS) * 512 + word;
#pragma unroll
        for (int c = 1; c < NC; c++) {
            unsigned m = __ballot_sync(0xffffffffu, bi == c);
            if (lane0) segbase[(c - 1) * 512] = m;
        }
        if (src == 0) {                      // student: logit>0.5 bitmaps
            unsigned* gbase = g_gt05 + (size_t)(b * NCLS) * 512 + word;
#pragma unroll
            for (int c = 1; c < NC; c++) {
                unsigned m = __ballot_sync(0xffffffffu, v[c] > 0.5f);
                if (lane0) gbase[(c - 1) * 512] = m;
            }
        }
    }

    // ---- grid-wide sense-reversing barrier (128 co-resident CTAs) ----
    // Helper CTAs (bid >= 104) only ARRIVE; they never consume post-barrier
    // data, so they exit without waiting for the release flip.
    __threadfence();
    __syncthreads();
    if (bid >= NPAIR * 4) {
        if (t == 0) {
            __threadfence();
            if (atomicAdd(&g_cnt, 1) == NCTA - 1) {
                g_cnt = 0;
                __threadfence();
                atomicExch(&g_release, my_sense ^ 1);
            }
        }
        return;
    }
    if (t == 0) {
        __threadfence();
        int ticket = atomicAdd(&g_cnt, 1);
        if (ticket == NCTA - 1) {
            g_cnt = 0;
            __threadfence();
            atomicExch(&g_release, my_sense ^ 1);
        } else {
            while (*(volatile int*)&g_release == my_sense) __nanosleep(32);
        }
        __threadfence();
    }
    __syncthreads();

    // ---- Stage B: one CTA per (pair, pass) ----
    int pair = bid >> 2;
    int pass = bid & 3;
    int b    = pair / NCLS;
    int cls  = 1 + (pair % NCLS);

    // load the three bitmaps (1 word per thread)
    segS[t] = g_seg[(size_t)((0 * NB + b) * NCLS + cls - 1) * 512 + t];
    segT[t] = g_seg[(size_t)((1 * NB + b) * NCLS + cls - 1) * 512 + t];
    g05[t]  = g_gt05[(size_t)(b * NCLS + cls - 1) * 512 + t];

    // fill gT padding rows with 255 (exactly 264 u32 words per region)
    {
        unsigned* p32 = (unsigned*)gT;
        if (t < 264) {
            p32[t] = 0xFFFFFFFFu;             // rows [0,8)
            p32[4488 + t] = 0xFFFFFFFFu;      // rows [136,144)
        }
    }
    __syncthreads();

    // word-parallel erosion: word t = (row t>>2, quarter t&3)
    int row = t >> 2, w = t & 3;
    unsigned ew, tw;
    {
        unsigned cs = segS[t];
        unsigned up = (row > 0)   ? segS[t - 4] : 0u;
        unsigned dn = (row < 127) ? segS[t + 4] : 0u;
        unsigned lf = (cs << 1) | (w > 0 ? (segS[t - 1] >> 31) : 0u);
        unsigned rg = (cs >> 1) | (w < 3 ? (segS[t + 1] << 31) : 0u);
        ew = cs & ~(cs & up & dn & lf & rg);

        unsigned ct = segT[t];
        unsigned u2 = (row > 0)   ? segT[t - 4] : 0u;
        unsigned d2 = (row < 127) ? segT[t + 4] : 0u;
        unsigned l2 = (ct << 1) | (w > 0 ? (segT[t - 1] >> 31) : 0u);
        unsigned r2 = (ct >> 1) | (w < 3 ? (segT[t + 1] << 31) : 0u);
        tw = ct & ~(ct & u2 & d2 & l2 & r2);
    }

    // seed bitmap for this pass (all-register)
    // pass 0: fgP = es & gt05   pass 1: ~fgP   pass 2: et   pass 3: ~et
    unsigned inv = (pass & 1) ? 0xffffffffu : 0u;
    unsigned sv  = ((pass < 2) ? (ew & g05[t]) : tw) ^ inv;
    Sm[t] = sv;
    // barrier: after this, seg/g05 region is dead -> list may overwrite
    int any = __syncthreads_or(sv != 0u);

    int jbase = w * 32;
    const float* lgb = stud + (size_t)(b * NC + cls) * 16384;

    // ---- Compaction: deterministic list of pixels where diff2 != 0 ----
    int n_tot;
    {
        unsigned m = ew | tw;
        int cnt = __popc(m);
        int lane = t & 31, wid = t >> 5;
        int pre = cnt;
#pragma unroll
        for (int o = 1; o < 32; o <<= 1) {
            int v = __shfl_up_sync(0xffffffffu, pre, o);
            if (lane >= o) pre += v;
        }
        if (lane == 31) s_wsum[wid] = pre;
        __syncthreads();
        int wbase = 0;
        for (int k = 0; k < wid; k++) wbase += s_wsum[k];
        n_tot = 0;
#pragma unroll
        for (int k = 0; k < 16; k++) n_tot += s_wsum[k];
        int ofs = wbase + pre - cnt;
        while (m) {
            int bit = __ffs(m) - 1;
            m &= m - 1;
            int j = jbase + bit;
            list[ofs++] = (unsigned short)(((unsigned)row << 9) |
                                           ((unsigned)j << 2)   |
                                           ((ew >> bit) & 1u)   |
                                           (((tw >> bit) & 1u) << 1));
        }
    }

    // ---- Phase 1: horizontal 1D distance, INTERLEAVED dual scans ----
    // Forward (index jj) and backward (index 31-jj) chains are independent,
    // so interleaving them halves the loop-carried-latency bound.
    {
        int ri = t & 127;
        int qd = t >> 7;
        unsigned W[4];
#pragma unroll
        for (int k = 0; k < 4; k++) W[k] = Sm[ri * 4 + k];
        unsigned Wq = W[qd];
        int lpos = -100000;
        for (int k = qd - 1; k >= 0; k--)
            if (W[k]) { lpos = 32 * k + (31 - __clz(W[k])); break; }
        int rpos = 100000;
        for (int k = qd + 1; k < 4; k++)
            if (W[k]) { rpos = 32 * k + (__ffs(W[k]) - 1); break; }

        int jb = qd * 32;
        int df[32], db[32];
        int d = jb - 1 - lpos;               // fwd chain seed
        int e = rpos - jb - 32;              // bwd chain seed
#pragma unroll
        for (int jj = 0; jj < 32; jj++) {
            d++;
            if ((Wq >> jj) & 1u) d = 0;
            df[jj] = d;
            int kk = 31 - jj;
            e++;
            if ((Wq >> kk) & 1u) e = 0;
            db[kk] = e;
        }
        unsigned* dst = (unsigned*)(gT + (ri + GPAD) * GCOLS + jb);
#pragma unroll
        for (int p = 0; p < 8; p++) {
            unsigned pk = 0;
#pragma unroll
            for (int h = 0; h < 4; h++) {
                int dd = min(df[4 * p + h], db[4 * p + h]);
                unsigned bb = (unsigned)min(dd, 255);  // >127 => INF
                pk |= bb << (8 * h);
            }
            dst[p] = pk;
        }
    }
    __syncthreads();   // list + gT complete

    // ---- Phase 2: seed-skip + g0==1 shortcut + R=6 search + fallback ----
    float acc = 0.f;
    if (any) {
        float fcls = (float)cls;
        for (int k = t; k < n_tot; k += NTHR) {
            unsigned e = list[k];
            int i = e >> 9;
            int j = (e >> 2) & 127;
            const unsigned char* g = gT + (i + GPAD) * GCOLS + j;
            int g0 = g[0];
            if (g0 == 0) continue;           // seed pixel: dt2 = 0
            float pred = (e & 1u) ? lgb[i * 128 + j] : 0.f;
            float targ = (e & 2u) ? fcls : 0.f;
            int best;
            if (g0 == 1) {
                best = 1;                    // all r>=1 candidates are >= 1
            } else {
                int m1 = min((int)g[ 1 * GCOLS], (int)g[-1 * GCOLS]);
                int m2 = min((int)g[ 2 * GCOLS], (int)g[-2 * GCOLS]);
                int m3 = min((int)g[ 3 * GCOLS], (int)g[-3 * GCOLS]);
                int m4 = min((int)g[ 4 * GCOLS], (int)g[-4 * GCOLS]);
                int m5 = min((int)g[ 5 * GCOLS], (int)g[-5 * GCOLS]);
                int m6 = min((int)g[ 6 * GCOLS], (int)g[-6 * GCOLS]);
                best = g0 * g0;
                best = min(best, m1 * m1 + 1);
                best = min(best, m2 * m2 + 4);
                best = min(best, m3 * m3 + 9);
                best = min(best, m4 * m4 + 16);
                best = min(best, m5 * m5 + 25);
                best = min(best, m6 * m6 + 36);
                if (best > 49) {   // exact fallback beyond R=6
#pragma unroll 1
                    for (int r = 7; r * r < best; r++) {
                        int lo = (r <= i + GPAD)      ? (int)g[-r * GCOLS] : 255;
                        int hi = (i + r < 128 + GPAD) ? (int)g[ r * GCOLS] : 255;
                        int v = min(lo, hi);
                        best = min(best, v * v + r * r);
                    }
                }
            }
            float dt2 = (best < 40000) ? (float)best : 0.f;
            float d = pred - targ;
            acc += d * d * dt2;
        }
    }

    // warp-shuffle reduction
#pragma unroll
    for (int o = 16; o; o >>= 1) acc += __shfl_down_sync(0xffffffffu, acc, o);
    if ((t & 31) == 0) s_warp[t >> 5] = acc;
    __syncthreads();

    // ---- finish: last CTA's warp 0 does the parallel log-combine ----
    if (t < 32) {
        if (t == 0) {
            float tot = 0.f;
#pragma unroll
            for (int k = 0; k < 16; k++) tot += s_warp[k];
            g_part[bid] = tot;
            __threadfence();
        }
        int last = 0;
        if (t == 0) last = (atomicAdd(&g_counter, 1) == NPAIR * 4 - 1);
        last = __shfl_sync(0xffffffffu, last, 0);
        if (last) {
            __threadfence();
            float v = 0.f;
            if (t < NPAIR) {
                volatile float* vp = g_part;
                float hd = (vp[4 * t + 0] + vp[4 * t + 1] +
                            vp[4 * t + 2] + vp[4 * t + 3]) * (1.f / 16384.f);
                v = logf(hd + 1.f);
            }
#pragma unroll
            for (int o = 16; o; o >>= 1)
                v += __shfl_down_sync(0xffffffffu, v, o);
            if (t == 0) {
                out[0] = 0.5f * v;   // (1 - LOSS_WEIGHT) * sum
                g_counter = 0;       // self-reset -> deterministic replays
            }
        }
    }
}

extern "C" void kernel_launch(void* const* d_in, const int* in_sizes, int n_in,
                              void* d_out, int out_size) {
    const float* stud  = (const float*)d_in[0];
    const float* teach = (const float*)d_in[1];
    float* out = (float*)d_out;

    const int SMEM = 19008 + 2048 + 32768;   // 53824 B dynamic
    cudaFuncSetAttribute(fused_kernel,
                         cudaFuncAttributeMaxDynamicSharedMemorySize, SMEM);
    fused_kernel<<<NCTA, NTHR, SMEM>>>(stud, teach, out);
}